// round 1
// baseline (speedup 1.0000x reference)
#include <cuda_runtime.h>
#include <math.h>

#define N_NODES 50000
#define D_FEAT  128
#define MAXNORM (1.0f - 4e-3f)   // (1 - eps)/sqrt(c), c=1

// Scratch for tangent-space features (allocation-free rule => __device__ global)
__device__ float g_tangent[(size_t)N_NODES * D_FEAT];

// ---------------------------------------------------------------------------
// Kernel A: x_tangent = logmap0(x) ; also zero the output accumulator.
// One warp per node row. lane i handles float4 at column 4*i.
// ---------------------------------------------------------------------------
__global__ void logmap0_zero_kernel(const float* __restrict__ x,
                                    float* __restrict__ out,
                                    int n_nodes) {
    int gtid = blockIdx.x * blockDim.x + threadIdx.x;
    int warp = gtid >> 5;
    int lane = gtid & 31;
    if (warp >= n_nodes) return;

    const float4* xr = reinterpret_cast<const float4*>(x) + (size_t)warp * (D_FEAT / 4);
    float4 v = xr[lane];

    float ss = v.x * v.x + v.y * v.y + v.z * v.z + v.w * v.w;
    #pragma unroll
    for (int o = 16; o; o >>= 1) ss += __shfl_xor_sync(0xffffffffu, ss, o);

    float n  = sqrtf(ss);
    float nm = fmaxf(n, 1e-15f);                 // p_norm clamp
    // artanh(clamp(nm, -1+1e-7, 1-1e-7)); nm >= 0 so only upper clamp matters
    float t   = fminf(nm, 1.0f - 1e-7f);
    float art = 0.5f * (log1pf(t) - log1pf(-t));
    float s   = art / nm;

    v.x *= s; v.y *= s; v.z *= s; v.w *= s;
    reinterpret_cast<float4*>(g_tangent)[(size_t)warp * (D_FEAT / 4) + lane] = v;

    // zero the accumulator (d_out) in the same pass
    reinterpret_cast<float4*>(out)[(size_t)warp * (D_FEAT / 4) + lane] =
        make_float4(0.f, 0.f, 0.f, 0.f);
}

// ---------------------------------------------------------------------------
// Kernel B: for each edge e: out[row[e]] += w[e] * tangent[col[e]]
// One warp per edge; vectorized no-return atomics (red.global.add.v4.f32).
// ---------------------------------------------------------------------------
__global__ void scatter_kernel(const int* __restrict__ erow,
                               const int* __restrict__ ecol,
                               const float* __restrict__ ew,
                               float* __restrict__ out,
                               int n_edges) {
    int gtid = blockIdx.x * blockDim.x + threadIdx.x;
    int warp = gtid >> 5;
    int lane = gtid & 31;
    if (warp >= n_edges) return;

    int   r = erow[warp];
    int   c = ecol[warp];
    float w = ew[warp];

    float4 v = reinterpret_cast<const float4*>(g_tangent)[(size_t)c * (D_FEAT / 4) + lane];
    float* dst = out + (size_t)r * D_FEAT + lane * 4;

    asm volatile("red.global.add.v4.f32 [%0], {%1, %2, %3, %4};"
                 :: "l"(dst), "f"(v.x * w), "f"(v.y * w), "f"(v.z * w), "f"(v.w * w)
                 : "memory");
}

// ---------------------------------------------------------------------------
// Kernel C: out = proj(expmap0(out))  (in-place, one warp per node).
// expmap0 scale: tanh(un)/un with un = max(||u||, 1e-15)
// resulting norm = ||u|| * tanh(un)/un = tanh(un) (for ||u|| > 1e-15)
// proj: if that norm > MAXNORM, rescale to MAXNORM.
// Combined factor: t = tanh(un); f = (t > MAXNORM ? MAXNORM : t) / un.
// ---------------------------------------------------------------------------
__global__ void expmap_proj_kernel(float* __restrict__ out, int n_nodes) {
    int gtid = blockIdx.x * blockDim.x + threadIdx.x;
    int warp = gtid >> 5;
    int lane = gtid & 31;
    if (warp >= n_nodes) return;

    float4* row = reinterpret_cast<float4*>(out) + (size_t)warp * (D_FEAT / 4);
    float4 v = row[lane];

    float ss = v.x * v.x + v.y * v.y + v.z * v.z + v.w * v.w;
    #pragma unroll
    for (int o = 16; o; o >>= 1) ss += __shfl_xor_sync(0xffffffffu, ss, o);

    float n  = sqrtf(ss);
    float un = fmaxf(n, 1e-15f);
    float t  = tanhf(un);
    // y = u * t/un has norm t; project if t > MAXNORM
    float f  = (t > MAXNORM ? MAXNORM : t) / un;

    v.x *= f; v.y *= f; v.z *= f; v.w *= f;
    row[lane] = v;
}

// ---------------------------------------------------------------------------
// Launch
// ---------------------------------------------------------------------------
extern "C" void kernel_launch(void* const* d_in, const int* in_sizes, int n_in,
                              void* d_out, int out_size) {
    const float* x    = (const float*)d_in[0];
    const int*   erow = (const int*)d_in[1];
    const int*   ecol = (const int*)d_in[2];
    const float* ew   = (const float*)d_in[3];
    float*       out  = (float*)d_out;

    int n_nodes = in_sizes[0] / D_FEAT;
    int n_edges = in_sizes[3];

    const int THREADS = 256;
    int blocksA = (n_nodes * 32 + THREADS - 1) / THREADS;
    int blocksB = (n_edges * 32 + THREADS - 1) / THREADS;

    logmap0_zero_kernel<<<blocksA, THREADS>>>(x, out, n_nodes);
    scatter_kernel<<<blocksB, THREADS>>>(erow, ecol, ew, out, n_edges);
    expmap_proj_kernel<<<blocksA, THREADS>>>(out, n_nodes);
}